// round 1
// baseline (speedup 1.0000x reference)
#include <cuda_runtime.h>
#include <math.h>

#define Bb 8
#define Cc 256
#define Hh 48
#define Ww 48
#define Nn 2304
#define NC (Nn*Cc)
static const long long NNL = (long long)Nn * (long long)Nn;

// Scratch (static device globals — allocation-guard safe)
__device__ float g_X[Bb*NC];        // (B,N,C)
__device__ float g_Q[Bb*NC];
__device__ float g_K[Bb*NC];
__device__ float g_nbr[Bb*NC];
__device__ float g_diag[Bb*Nn];
__device__ float g_S[(long long)Bb*Nn*Nn];   // logits -> probs (diag zeroed)

// ---------------------------------------------------------------------------
// 1) Pack: x (B,C,N) -> X (B,N,C), 32x32 smem transpose tiles
// ---------------------------------------------------------------------------
__global__ void k_pack(const float* __restrict__ x) {
    __shared__ float t[32][33];
    int b = blockIdx.z;
    int n0 = blockIdx.x * 32, c0 = blockIdx.y * 32;
    int tx = threadIdx.x, ty = threadIdx.y;
    const float* xb = x + (size_t)b * Cc * Nn;
    #pragma unroll
    for (int i = 0; i < 4; i++)
        t[ty + 8*i][tx] = xb[(size_t)(c0 + ty + 8*i) * Nn + n0 + tx];
    __syncthreads();
    float* Xb = g_X + b * NC;
    #pragma unroll
    for (int i = 0; i < 4; i++)
        Xb[(size_t)(n0 + ty + 8*i) * Cc + c0 + tx] = t[tx][ty + 8*i];
}

// ---------------------------------------------------------------------------
// 2) Dual projection: Q = X @ phi^T, K = X @ psi^T   (per batch, N x C x C)
//    64x64 tile, BK=16, 256 threads, 4x4 microtile
// ---------------------------------------------------------------------------
__global__ void __launch_bounds__(256) k_qk(const float* __restrict__ phi,
                                            const float* __restrict__ psi) {
    int b  = blockIdx.z;
    int n0 = blockIdx.y * 64;   // rows over N
    int d0 = blockIdx.x * 64;   // cols over C (output dim)
    const float* A = g_X + b * NC;

    __shared__ float As[64][16];
    __shared__ float Bs0[16][64];
    __shared__ float Bs1[16][64];

    int tid = threadIdx.x;
    int tx = tid % 16, ty = tid / 16;
    int lrow = tid / 4, lc4 = (tid % 4) * 4;

    float acc0[4][4]; float acc1[4][4];
    #pragma unroll
    for (int i = 0; i < 4; i++)
        #pragma unroll
        for (int j = 0; j < 4; j++) { acc0[i][j] = 0.f; acc1[i][j] = 0.f; }

    for (int k0 = 0; k0 < Cc; k0 += 16) {
        float4 av = *(const float4*)&A[(size_t)(n0 + lrow) * Cc + k0 + lc4];
        *(float4*)&As[lrow][lc4] = av;
        float4 b0 = *(const float4*)&phi[(size_t)(d0 + lrow) * Cc + k0 + lc4];
        float4 b1 = *(const float4*)&psi[(size_t)(d0 + lrow) * Cc + k0 + lc4];
        Bs0[lc4+0][lrow] = b0.x; Bs0[lc4+1][lrow] = b0.y;
        Bs0[lc4+2][lrow] = b0.z; Bs0[lc4+3][lrow] = b0.w;
        Bs1[lc4+0][lrow] = b1.x; Bs1[lc4+1][lrow] = b1.y;
        Bs1[lc4+2][lrow] = b1.z; Bs1[lc4+3][lrow] = b1.w;
        __syncthreads();
        #pragma unroll
        for (int k = 0; k < 16; k++) {
            float a[4], u[4], v[4];
            #pragma unroll
            for (int i = 0; i < 4; i++) a[i] = As[ty*4 + i][k];
            #pragma unroll
            for (int j = 0; j < 4; j++) { u[j] = Bs0[k][tx*4 + j]; v[j] = Bs1[k][tx*4 + j]; }
            #pragma unroll
            for (int i = 0; i < 4; i++)
                #pragma unroll
                for (int j = 0; j < 4; j++) {
                    acc0[i][j] += a[i] * u[j];
                    acc1[i][j] += a[i] * v[j];
                }
        }
        __syncthreads();
    }
    float* Qb = g_Q + b * NC;
    float* Kb = g_K + b * NC;
    #pragma unroll
    for (int i = 0; i < 4; i++) {
        float4 q, k4;
        q.x = acc0[i][0]; q.y = acc0[i][1]; q.z = acc0[i][2]; q.w = acc0[i][3];
        k4.x = acc1[i][0]; k4.y = acc1[i][1]; k4.z = acc1[i][2]; k4.w = acc1[i][3];
        *(float4*)&Qb[(size_t)(n0 + ty*4 + i) * Cc + d0 + tx*4] = q;
        *(float4*)&Kb[(size_t)(n0 + ty*4 + i) * Cc + d0 + tx*4] = k4;
    }
}

// ---------------------------------------------------------------------------
// 3) Logits: L = Q @ K^T (per batch, N x N x C) -> g_S
// ---------------------------------------------------------------------------
__global__ void __launch_bounds__(256) k_logits() {
    int b  = blockIdx.z;
    int n0 = blockIdx.y * 64;   // Q rows
    int m0 = blockIdx.x * 64;   // K rows (output cols)
    const float* A  = g_Q + b * NC;
    const float* Bm = g_K + b * NC;

    __shared__ float As[64][16];
    __shared__ float Bs[16][64];

    int tid = threadIdx.x;
    int tx = tid % 16, ty = tid / 16;
    int lrow = tid / 4, lc4 = (tid % 4) * 4;

    float acc[4][4];
    #pragma unroll
    for (int i = 0; i < 4; i++)
        #pragma unroll
        for (int j = 0; j < 4; j++) acc[i][j] = 0.f;

    for (int k0 = 0; k0 < Cc; k0 += 16) {
        float4 av = *(const float4*)&A[(size_t)(n0 + lrow) * Cc + k0 + lc4];
        *(float4*)&As[lrow][lc4] = av;
        float4 bv = *(const float4*)&Bm[(size_t)(m0 + lrow) * Cc + k0 + lc4];
        Bs[lc4+0][lrow] = bv.x; Bs[lc4+1][lrow] = bv.y;
        Bs[lc4+2][lrow] = bv.z; Bs[lc4+3][lrow] = bv.w;
        __syncthreads();
        #pragma unroll
        for (int k = 0; k < 16; k++) {
            float a[4], u[4];
            #pragma unroll
            for (int i = 0; i < 4; i++) a[i] = As[ty*4 + i][k];
            #pragma unroll
            for (int j = 0; j < 4; j++) u[j] = Bs[k][tx*4 + j];
            #pragma unroll
            for (int i = 0; i < 4; i++)
                #pragma unroll
                for (int j = 0; j < 4; j++) acc[i][j] += a[i] * u[j];
        }
        __syncthreads();
    }
    float* Cp = g_S + (long long)b * NNL;
    #pragma unroll
    for (int i = 0; i < 4; i++) {
        float4 o;
        o.x = acc[i][0]; o.y = acc[i][1]; o.z = acc[i][2]; o.w = acc[i][3];
        *(float4*)&Cp[(long long)(n0 + ty*4 + i) * Nn + m0 + tx*4] = o;
    }
}

// ---------------------------------------------------------------------------
// 4) Row softmax + threshold; capture diag prob, zero diagonal in place
// ---------------------------------------------------------------------------
__global__ void __launch_bounds__(256) k_softmax() {
    int b = blockIdx.y, n = blockIdx.x, tid = threadIdx.x;
    float* row = g_S + (long long)b * NNL + (long long)n * Nn;
    __shared__ float red[256];

    float mx = -1e30f;
    for (int m = tid; m < Nn; m += 256) mx = fmaxf(mx, row[m]);
    red[tid] = mx; __syncthreads();
    for (int s = 128; s > 0; s >>= 1) {
        if (tid < s) red[tid] = fmaxf(red[tid], red[tid + s]);
        __syncthreads();
    }
    mx = red[0]; __syncthreads();

    float sum = 0.f;
    for (int m = tid; m < Nn; m += 256) sum += __expf(row[m] - mx);
    red[tid] = sum; __syncthreads();
    for (int s = 128; s > 0; s >>= 1) {
        if (tid < s) red[tid] += red[tid + s];
        __syncthreads();
    }
    float inv = 1.f / red[0];

    for (int m = tid; m < Nn; m += 256) {
        float p = __expf(row[m] - mx) * inv;
        if (p < 0.01f) p = 0.f;
        if (m == n) { g_diag[b * Nn + n] = p; p = 0.f; }
        row[m] = p;
    }
}

// ---------------------------------------------------------------------------
// 5) nbr = S' @ X  (per batch, N x C, K = N)
// ---------------------------------------------------------------------------
__global__ void __launch_bounds__(256) k_nbr() {
    int b  = blockIdx.z;
    int n0 = blockIdx.y * 64;   // rows over N
    int d0 = blockIdx.x * 64;   // cols over C
    const float* A  = g_S + (long long)b * NNL;
    const float* Bm = g_X + b * NC;

    __shared__ float As[64][16];
    __shared__ float Bs[16][64];

    int tid = threadIdx.x;
    int tx = tid % 16, ty = tid / 16;
    int arow = tid / 4, ac4 = (tid % 4) * 4;
    int bk = tid / 16, bc4 = (tid % 16) * 4;

    float acc[4][4];
    #pragma unroll
    for (int i = 0; i < 4; i++)
        #pragma unroll
        for (int j = 0; j < 4; j++) acc[i][j] = 0.f;

    for (int k0 = 0; k0 < Nn; k0 += 16) {
        float4 av = *(const float4*)&A[(long long)(n0 + arow) * Nn + k0 + ac4];
        *(float4*)&As[arow][ac4] = av;
        float4 bv = *(const float4*)&Bm[(size_t)(k0 + bk) * Cc + d0 + bc4];
        *(float4*)&Bs[bk][bc4] = bv;
        __syncthreads();
        #pragma unroll
        for (int k = 0; k < 16; k++) {
            float a[4], u[4];
            #pragma unroll
            for (int i = 0; i < 4; i++) a[i] = As[ty*4 + i][k];
            #pragma unroll
            for (int j = 0; j < 4; j++) u[j] = Bs[k][tx*4 + j];
            #pragma unroll
            for (int i = 0; i < 4; i++)
                #pragma unroll
                for (int j = 0; j < 4; j++) acc[i][j] += a[i] * u[j];
        }
        __syncthreads();
    }
    float* Cp = g_nbr + b * NC;
    #pragma unroll
    for (int i = 0; i < 4; i++) {
        float4 o;
        o.x = acc[i][0]; o.y = acc[i][1]; o.z = acc[i][2]; o.w = acc[i][3];
        *(float4*)&Cp[(size_t)(n0 + ty*4 + i) * Cc + d0 + tx*4] = o;
    }
}

// ---------------------------------------------------------------------------
// 6) Add 4-neighbor grid adjacency messages: nbr[n] += sum X[grid neighbors]
// ---------------------------------------------------------------------------
__global__ void k_addnbr() {
    int b = blockIdx.y, n = blockIdx.x, c = threadIdx.x;
    int y = n / Ww, x = n % Ww;
    const float* Xb = g_X + b * NC;
    float s = 0.f;
    if (y > 0)      s += Xb[(size_t)(n - Ww) * Cc + c];
    if (y < Hh - 1) s += Xb[(size_t)(n + Ww) * Cc + c];
    if (x > 0)      s += Xb[(size_t)(n - 1) * Cc + c];
    if (x < Ww - 1) s += Xb[(size_t)(n + 1) * Cc + c];
    g_nbr[(size_t)b * NC + (size_t)n * Cc + c] += s;
}

// ---------------------------------------------------------------------------
// 7) Final: out[b,d,n] = relu( sum_c (X[n,c]*(1+diag[n]))*w0[d,c] + nbr[n,c]*w1[d,c] )
//    Tile: rows = d (64), cols = n (64); writes coalesced over n.
// ---------------------------------------------------------------------------
__global__ void __launch_bounds__(256) k_final(const float* __restrict__ w0,
                                               const float* __restrict__ w1,
                                               float* __restrict__ out) {
    int b  = blockIdx.z;
    int d0 = blockIdx.y * 64;
    int n0 = blockIdx.x * 64;

    __shared__ float As0[64][16];   // w0 tile [d][c]
    __shared__ float As1[64][16];   // w1 tile
    __shared__ float Bs0[16][64];   // Xd  [c][n]
    __shared__ float Bs1[16][64];   // nbr [c][n]

    int tid = threadIdx.x;
    int tx = tid % 16, ty = tid / 16;
    int lrow = tid / 4, lc4 = (tid % 4) * 4;

    const float* Xb = g_X + b * NC;
    const float* Nb = g_nbr + b * NC;
    float dscale = 1.f + g_diag[b * Nn + n0 + lrow];

    float acc[4][4];
    #pragma unroll
    for (int i = 0; i < 4; i++)
        #pragma unroll
        for (int j = 0; j < 4; j++) acc[i][j] = 0.f;

    for (int k0 = 0; k0 < Cc; k0 += 16) {
        float4 a0 = *(const float4*)&w0[(size_t)(d0 + lrow) * Cc + k0 + lc4];
        float4 a1 = *(const float4*)&w1[(size_t)(d0 + lrow) * Cc + k0 + lc4];
        *(float4*)&As0[lrow][lc4] = a0;
        *(float4*)&As1[lrow][lc4] = a1;
        float4 xv = *(const float4*)&Xb[(size_t)(n0 + lrow) * Cc + k0 + lc4];
        float4 nv = *(const float4*)&Nb[(size_t)(n0 + lrow) * Cc + k0 + lc4];
        Bs0[lc4+0][lrow] = xv.x * dscale; Bs0[lc4+1][lrow] = xv.y * dscale;
        Bs0[lc4+2][lrow] = xv.z * dscale; Bs0[lc4+3][lrow] = xv.w * dscale;
        Bs1[lc4+0][lrow] = nv.x; Bs1[lc4+1][lrow] = nv.y;
        Bs1[lc4+2][lrow] = nv.z; Bs1[lc4+3][lrow] = nv.w;
        __syncthreads();
        #pragma unroll
        for (int k = 0; k < 16; k++) {
            float a[4], c0v[4], u[4], v[4];
            #pragma unroll
            for (int i = 0; i < 4; i++) { a[i] = As0[ty*4 + i][k]; c0v[i] = As1[ty*4 + i][k]; }
            #pragma unroll
            for (int j = 0; j < 4; j++) { u[j] = Bs0[k][tx*4 + j]; v[j] = Bs1[k][tx*4 + j]; }
            #pragma unroll
            for (int i = 0; i < 4; i++)
                #pragma unroll
                for (int j = 0; j < 4; j++)
                    acc[i][j] += a[i] * u[j] + c0v[i] * v[j];
        }
        __syncthreads();
    }
    #pragma unroll
    for (int i = 0; i < 4; i++) {
        float4 o;
        o.x = fmaxf(acc[i][0], 0.f); o.y = fmaxf(acc[i][1], 0.f);
        o.z = fmaxf(acc[i][2], 0.f); o.w = fmaxf(acc[i][3], 0.f);
        int d = d0 + ty*4 + i;
        *(float4*)&out[((size_t)b * Cc + d) * Nn + n0 + tx*4] = o;
    }
}

// ---------------------------------------------------------------------------
extern "C" void kernel_launch(void* const* d_in, const int* in_sizes, int n_in,
                              void* d_out, int out_size) {
    const float* x    = (const float*)d_in[0];
    const float* phi  = (const float*)d_in[1];
    const float* psi  = (const float*)d_in[2];
    const float* w0   = (const float*)d_in[3];
    const float* w1   = (const float*)d_in[4];
    float* out = (float*)d_out;

    // 1) pack/transpose
    k_pack<<<dim3(Nn/32, Cc/32, Bb), dim3(32, 8)>>>(x);
    // 2) Q,K projections (dual)
    k_qk<<<dim3(Cc/64, Nn/64, Bb), 256>>>(phi, psi);
    // 3) logits
    k_logits<<<dim3(Nn/64, Nn/64, Bb), 256>>>();
    // 4) softmax + threshold + diag extraction
    k_softmax<<<dim3(Nn, Bb), 256>>>();
    // 5) attention message S' @ X
    k_nbr<<<dim3(Cc/64, Nn/64, Bb), 256>>>();
    // 6) grid-adjacency messages
    k_addnbr<<<dim3(Nn, Bb), Cc>>>();
    // 7) final dual GEMM + relu + transpose to (B,C,H,W)
    k_final<<<dim3(Nn/64, Cc/64, Bb), 256>>>(w0, w1, out);
}

// round 4
// speedup vs baseline: 2.2223x; 2.2223x over previous
#include <cuda_runtime.h>
#include <cuda_bf16.h>
#include <cstdint>
#include <math.h>

#define Bb 8
#define Cc 256
#define Hh 48
#define Ww 48
#define Nn 2304
#define NC (Nn*Cc)
#define CAP 112
static const long long NNL = (long long)Nn * (long long)Nn;

// ---------------- scratch (static device globals — allocation-guard safe) ----
__device__ float g_X[Bb*NC];                     // (B,N,C) fp32
__device__ float g_nbr[Bb*NC];                   // (B,N,C) fp32
__device__ float g_diag[Bb*Nn];
__device__ float g_S[(long long)Bb*Nn*Nn];       // logits fp32
__device__ __nv_bfloat16 g_Qhi[Bb*NC], g_Qlo[Bb*NC];
__device__ __nv_bfloat16 g_Khi[Bb*NC], g_Klo[Bb*NC];
__device__ int   g_sidx[Bb*Nn*CAP];              // sparse S: col indices
__device__ float g_sval[Bb*Nn*CAP];              // sparse S: probs
__device__ int   g_scnt[Bb*Nn];

// ---------------- PTX helpers (all base-target features: sm_80 era) ----------
__device__ __forceinline__ uint32_t smem_u32(const void* p) {
    uint32_t a;
    asm("{ .reg .u64 t; cvta.to.shared.u64 t, %1; cvt.u32.u64 %0, t; }" : "=r"(a) : "l"(p));
    return a;
}
__device__ __forceinline__ void cp16(uint32_t dst, const void* src) {
    asm volatile("cp.async.cg.shared.global [%0], [%1], 16;" :: "r"(dst), "l"(src));
}
#define CP_COMMIT() asm volatile("cp.async.commit_group;" ::: "memory")
#define CP_WAIT(n)  asm volatile("cp.async.wait_group %0;" :: "n"(n) : "memory")

#define LDSM4(r, a) \
    asm volatile("ldmatrix.sync.aligned.m8n8.x4.shared.b16 {%0,%1,%2,%3}, [%4];" \
        : "=r"((r)[0]),"=r"((r)[1]),"=r"((r)[2]),"=r"((r)[3]) : "r"(a))
#define LDSM2(r, a) \
    asm volatile("ldmatrix.sync.aligned.m8n8.x2.shared.b16 {%0,%1}, [%2];" \
        : "=r"((r)[0]),"=r"((r)[1]) : "r"(a))
#define MMA16816(d, a, b) \
    asm volatile("mma.sync.aligned.m16n8k16.row.col.f32.bf16.bf16.f32 " \
        "{%0,%1,%2,%3}, {%4,%5,%6,%7}, {%8,%9}, {%0,%1,%2,%3};" \
        : "+f"((d)[0]),"+f"((d)[1]),"+f"((d)[2]),"+f"((d)[3]) \
        : "r"((a)[0]),"r"((a)[1]),"r"((a)[2]),"r"((a)[3]), "r"((b)[0]),"r"((b)[1]))

// ---------------------------------------------------------------------------
// 1) Pack: x (B,C,N) -> X (B,N,C)
// ---------------------------------------------------------------------------
__global__ void k_pack(const float* __restrict__ x) {
    __shared__ float t[32][33];
    int b = blockIdx.z;
    int n0 = blockIdx.x * 32, c0 = blockIdx.y * 32;
    int tx = threadIdx.x, ty = threadIdx.y;
    const float* xb = x + (size_t)b * Cc * Nn;
    #pragma unroll
    for (int i = 0; i < 4; i++)
        t[ty + 8*i][tx] = xb[(size_t)(c0 + ty + 8*i) * Nn + n0 + tx];
    __syncthreads();
    float* Xb = g_X + b * NC;
    #pragma unroll
    for (int i = 0; i < 4; i++)
        Xb[(size_t)(n0 + ty + 8*i) * Cc + c0 + tx] = t[tx][ty + 8*i];
}

// ---------------------------------------------------------------------------
// 2) Dual projection Q/K (SIMT), fp32 accumulate, emit bf16 hi/lo split
// ---------------------------------------------------------------------------
__global__ void __launch_bounds__(256) k_qk(const float* __restrict__ phi,
                                            const float* __restrict__ psi) {
    int b  = blockIdx.z;
    int n0 = blockIdx.y * 64;
    int d0 = blockIdx.x * 64;
    const float* A = g_X + b * NC;

    __shared__ float As[64][16];
    __shared__ float Bs0[16][64];
    __shared__ float Bs1[16][64];

    int tid = threadIdx.x;
    int tx = tid % 16, ty = tid / 16;
    int lrow = tid / 4, lc4 = (tid % 4) * 4;

    float acc0[4][4], acc1[4][4];
    #pragma unroll
    for (int i = 0; i < 4; i++)
        #pragma unroll
        for (int j = 0; j < 4; j++) { acc0[i][j] = 0.f; acc1[i][j] = 0.f; }

    for (int k0 = 0; k0 < Cc; k0 += 16) {
        float4 av = *(const float4*)&A[(size_t)(n0 + lrow) * Cc + k0 + lc4];
        *(float4*)&As[lrow][lc4] = av;
        float4 b0 = *(const float4*)&phi[(size_t)(d0 + lrow) * Cc + k0 + lc4];
        float4 b1 = *(const float4*)&psi[(size_t)(d0 + lrow) * Cc + k0 + lc4];
        Bs0[lc4+0][lrow] = b0.x; Bs0[lc4+1][lrow] = b0.y;
        Bs0[lc4+2][lrow] = b0.z; Bs0[lc4+3][lrow] = b0.w;
        Bs1[lc4+0][lrow] = b1.x; Bs1[lc4+1][lrow] = b1.y;
        Bs1[lc4+2][lrow] = b1.z; Bs1[lc4+3][lrow] = b1.w;
        __syncthreads();
        #pragma unroll
        for (int k = 0; k < 16; k++) {
            float a[4], u[4], v[4];
            #pragma unroll
            for (int i = 0; i < 4; i++) a[i] = As[ty*4 + i][k];
            #pragma unroll
            for (int j = 0; j < 4; j++) { u[j] = Bs0[k][tx*4 + j]; v[j] = Bs1[k][tx*4 + j]; }
            #pragma unroll
            for (int i = 0; i < 4; i++)
                #pragma unroll
                for (int j = 0; j < 4; j++) {
                    acc0[i][j] += a[i] * u[j];
                    acc1[i][j] += a[i] * v[j];
                }
        }
        __syncthreads();
    }
    #pragma unroll
    for (int i = 0; i < 4; i++) {
        size_t off = (size_t)b * NC + (size_t)(n0 + ty*4 + i) * Cc + d0 + tx*4;
        #pragma unroll
        for (int j = 0; j < 4; j++) {
            float q = acc0[i][j], kk = acc1[i][j];
            __nv_bfloat16 qh = __float2bfloat16(q);
            __nv_bfloat16 kh = __float2bfloat16(kk);
            g_Qhi[off + j] = qh;
            g_Qlo[off + j] = __float2bfloat16(q - __bfloat162float(qh));
            g_Khi[off + j] = kh;
            g_Klo[off + j] = __float2bfloat16(kk - __bfloat162float(kh));
        }
    }
}

// ---------------------------------------------------------------------------
// 3) Logits via mma.sync bf16 3-term split: L = Q @ K^T  (128x128 CTA tile)
//    8 warps: warp grid 2(m) x 4(n), warp tile 64x32
// ---------------------------------------------------------------------------
#define SSTR 40                    // padded row stride (elements)
#define TILE_E (128*SSTR)          // elements per tile buffer
// tiles per stage: 0=Ah 1=Al 2=Bh 3=Bl
#define SM_LOGITS_BYTES (2*4*TILE_E*2)

__device__ __forceinline__ void load_stage(__nv_bfloat16* sm, int stage,
        const __nv_bfloat16* Ah, const __nv_bfloat16* Al,
        const __nv_bfloat16* Bh, const __nv_bfloat16* Bl,
        int k0, int tid) {
    const __nv_bfloat16* srcs[4] = {Ah, Al, Bh, Bl};
    #pragma unroll
    for (int t = 0; t < 4; t++) {
        __nv_bfloat16* dst = sm + (stage*4 + t) * TILE_E;
        #pragma unroll
        for (int i = 0; i < 2; i++) {
            int chunk = i * 256 + tid;
            int r = chunk >> 2, c4 = chunk & 3;
            cp16(smem_u32(dst + r*SSTR + c4*8), srcs[t] + (size_t)r*Cc + k0 + c4*8);
        }
    }
}

__global__ void __launch_bounds__(256) k_logits_mma() {
    extern __shared__ __nv_bfloat16 sm[];
    int tid = threadIdx.x, wid = tid >> 5, lane = tid & 31;
    int b = blockIdx.z;
    int arow = blockIdx.y * 128;
    int brow = blockIdx.x * 128;

    const __nv_bfloat16* Ah = g_Qhi + (size_t)b*NC + (size_t)arow*Cc;
    const __nv_bfloat16* Al = g_Qlo + (size_t)b*NC + (size_t)arow*Cc;
    const __nv_bfloat16* Bh = g_Khi + (size_t)b*NC + (size_t)brow*Cc;
    const __nv_bfloat16* Bl = g_Klo + (size_t)b*NC + (size_t)brow*Cc;

    int wm = (wid & 1) * 64;       // warp m offset in CTA tile
    int wn = (wid >> 1) * 32;      // warp n offset

    float acc[4][4][4];
    #pragma unroll
    for (int mi = 0; mi < 4; mi++)
        #pragma unroll
        for (int ni = 0; ni < 4; ni++)
            #pragma unroll
            for (int r = 0; r < 4; r++) acc[mi][ni][r] = 0.f;

    load_stage(sm, 0, Ah, Al, Bh, Bl, 0, tid);
    CP_COMMIT();

    for (int ch = 0; ch < 8; ch++) {
        if (ch < 7) {
            load_stage(sm, (ch + 1) & 1, Ah, Al, Bh, Bl, (ch + 1) * 32, tid);
            CP_COMMIT();
            CP_WAIT(1);
        } else {
            CP_WAIT(0);
        }
        __syncthreads();

        int st = ch & 1;
        const __nv_bfloat16* tAh = sm + (st*4 + 0) * TILE_E;
        const __nv_bfloat16* tAl = sm + (st*4 + 1) * TILE_E;
        const __nv_bfloat16* tBh = sm + (st*4 + 2) * TILE_E;
        const __nv_bfloat16* tBl = sm + (st*4 + 3) * TILE_E;

        #pragma unroll
        for (int ks = 0; ks < 2; ks++) {
            uint32_t ah[4][4], al[4][4], bh[4][2], bl[4][2];
            int arl = lane & 15, ach = lane >> 4;          // x4 addressing
            int brl = lane & 7,  bch = (lane & 15) >> 3;   // x2 addressing
            #pragma unroll
            for (int mi = 0; mi < 4; mi++) {
                uint32_t aoff = smem_u32(tAh + (wm + mi*16 + arl)*SSTR + ks*16 + ach*8);
                LDSM4(ah[mi], aoff);
                uint32_t aoff2 = smem_u32(tAl + (wm + mi*16 + arl)*SSTR + ks*16 + ach*8);
                LDSM4(al[mi], aoff2);
            }
            #pragma unroll
            for (int ni = 0; ni < 4; ni++) {
                uint32_t boff = smem_u32(tBh + (wn + ni*8 + brl)*SSTR + ks*16 + bch*8);
                LDSM2(bh[ni], boff);
                uint32_t boff2 = smem_u32(tBl + (wn + ni*8 + brl)*SSTR + ks*16 + bch*8);
                LDSM2(bl[ni], boff2);
            }
            #pragma unroll
            for (int mi = 0; mi < 4; mi++)
                #pragma unroll
                for (int ni = 0; ni < 4; ni++) {
                    MMA16816(acc[mi][ni], ah[mi], bh[ni]);
                    MMA16816(acc[mi][ni], ah[mi], bl[ni]);
                    MMA16816(acc[mi][ni], al[mi], bh[ni]);
                }
        }
        __syncthreads();
    }

    // epilogue: C fragment -> g_S
    float* Cp = g_S + (size_t)b * NNL;
    int r0 = arow + wm + (lane >> 2);
    int c0 = brow + wn + (lane & 3) * 2;
    #pragma unroll
    for (int mi = 0; mi < 4; mi++)
        #pragma unroll
        for (int ni = 0; ni < 4; ni++) {
            float* p0 = Cp + (size_t)(r0 + mi*16) * Nn + c0 + ni*8;
            p0[0] = acc[mi][ni][0]; p0[1] = acc[mi][ni][1];
            float* p1 = p0 + (size_t)8 * Nn;
            p1[0] = acc[mi][ni][2]; p1[1] = acc[mi][ni][3];
        }
}

// ---------------------------------------------------------------------------
// 4) Row softmax + threshold -> sparse (idx,val) list (deterministic order)
// ---------------------------------------------------------------------------
__global__ void __launch_bounds__(256) k_softmax_sparse() {
    __shared__ float probs[Nn];
    __shared__ float red[256];
    __shared__ int warp_cnt[8];
    __shared__ int seg_base;

    int b = blockIdx.y, n = blockIdx.x, tid = threadIdx.x;
    int wid = tid >> 5, lane = tid & 31;
    const float* row = g_S + (long long)b * NNL + (long long)n * Nn;

    float mx = -1e30f;
    for (int m = tid; m < Nn; m += 256) {
        float v = row[m];
        probs[m] = v;
        mx = fmaxf(mx, v);
    }
    red[tid] = mx; __syncthreads();
    for (int s = 128; s > 0; s >>= 1) {
        if (tid < s) red[tid] = fmaxf(red[tid], red[tid + s]);
        __syncthreads();
    }
    mx = red[0]; __syncthreads();

    float sum = 0.f;
    for (int m = tid; m < Nn; m += 256) sum += __expf(probs[m] - mx);
    red[tid] = sum; __syncthreads();
    for (int s = 128; s > 0; s >>= 1) {
        if (tid < s) red[tid] += red[tid + s];
        __syncthreads();
    }
    float inv = 1.f / red[0];
    if (tid == 0) seg_base = 0;
    __syncthreads();

    int* idx = g_sidx + ((size_t)b * Nn + n) * CAP;
    float* val = g_sval + ((size_t)b * Nn + n) * CAP;

    for (int seg = 0; seg < Nn / 256; seg++) {
        int m = seg * 256 + tid;
        float p = __expf(probs[m] - mx) * inv;
        if (p < 0.01f) p = 0.f;
        if (m == n) {
            g_diag[b * Nn + n] = p;   // thresholded diag prob
            p = 0.f;                  // excluded from sparse list
        }
        bool keep = (p != 0.f);
        unsigned mask = __ballot_sync(0xffffffffu, keep);
        int pre = __popc(mask & ((1u << lane) - 1));
        if (lane == 0) warp_cnt[wid] = __popc(mask);
        __syncthreads();
        int wbase = seg_base;
        for (int w = 0; w < wid; w++) wbase += warp_cnt[w];
        if (keep) { idx[wbase + pre] = m; val[wbase + pre] = p; }
        __syncthreads();
        if (tid == 0) {
            int t = 0;
            for (int w = 0; w < 8; w++) t += warp_cnt[w];
            seg_base += t;
        }
        __syncthreads();
    }
    if (tid == 0) g_scnt[b * Nn + n] = seg_base;
}

// ---------------------------------------------------------------------------
// 5) Sparse nbr: nbr[n,:] = sum_i p_i X[m_i,:] + grid-adjacent X rows
// ---------------------------------------------------------------------------
__global__ void __launch_bounds__(256) k_nbr_sparse() {
    int b = blockIdx.y, n = blockIdx.x, c = threadIdx.x;
    int y = n / Ww, x = n % Ww;
    const float* Xb = g_X + b * NC;

    float acc = 0.f;
    if (y > 0)      acc += Xb[(size_t)(n - Ww) * Cc + c];
    if (y < Hh - 1) acc += Xb[(size_t)(n + Ww) * Cc + c];
    if (x > 0)      acc += Xb[(size_t)(n - 1) * Cc + c];
    if (x < Ww - 1) acc += Xb[(size_t)(n + 1) * Cc + c];

    int cnt = g_scnt[b * Nn + n];
    const int* idx = g_sidx + ((size_t)b * Nn + n) * CAP;
    const float* val = g_sval + ((size_t)b * Nn + n) * CAP;
    for (int i = 0; i < cnt; i++)
        acc += val[i] * Xb[(size_t)idx[i] * Cc + c];

    g_nbr[(size_t)b * NC + (size_t)n * Cc + c] = acc;
}

// ---------------------------------------------------------------------------
// 6) Final dual GEMM + relu + transpose to (B,C,H,W)
// ---------------------------------------------------------------------------
__global__ void __launch_bounds__(256) k_final(const float* __restrict__ w0,
                                               const float* __restrict__ w1,
                                               float* __restrict__ out) {
    int b  = blockIdx.z;
    int d0 = blockIdx.y * 64;
    int n0 = blockIdx.x * 64;

    __shared__ float As0[64][16];
    __shared__ float As1[64][16];
    __shared__ float Bs0[16][64];
    __shared__ float Bs1[16][64];

    int tid = threadIdx.x;
    int tx = tid % 16, ty = tid / 16;
    int lrow = tid / 4, lc4 = (tid % 4) * 4;

    const float* Xb = g_X + b * NC;
    const float* Nb = g_nbr + b * NC;
    float dscale = 1.f + g_diag[b * Nn + n0 + lrow];

    float acc[4][4];
    #pragma unroll
    for (int i = 0; i < 4; i++)
        #pragma unroll
        for (int j = 0; j < 4; j++) acc[i][j] = 0.f;

    for (int k0 = 0; k0 < Cc; k0 += 16) {
        float4 a0 = *(const float4*)&w0[(size_t)(d0 + lrow) * Cc + k0 + lc4];
        float4 a1 = *(const float4*)&w1[(size_t)(d0 + lrow) * Cc + k0 + lc4];
        *(float4*)&As0[lrow][lc4] = a0;
        *(float4*)&As1[lrow][lc4] = a1;
        float4 xv = *(const float4*)&Xb[(size_t)(n0 + lrow) * Cc + k0 + lc4];
        float4 nv = *(const float4*)&Nb[(size_t)(n0 + lrow) * Cc + k0 + lc4];
        Bs0[lc4+0][lrow] = xv.x * dscale; Bs0[lc4+1][lrow] = xv.y * dscale;
        Bs0[lc4+2][lrow] = xv.z * dscale; Bs0[lc4+3][lrow] = xv.w * dscale;
        Bs1[lc4+0][lrow] = nv.x; Bs1[lc4+1][lrow] = nv.y;
        Bs1[lc4+2][lrow] = nv.z; Bs1[lc4+3][lrow] = nv.w;
        __syncthreads();
        #pragma unroll
        for (int k = 0; k < 16; k++) {
            float a[4], c0v[4], u[4], v[4];
            #pragma unroll
            for (int i = 0; i < 4; i++) { a[i] = As0[ty*4 + i][k]; c0v[i] = As1[ty*4 + i][k]; }
            #pragma unroll
            for (int j = 0; j < 4; j++) { u[j] = Bs0[k][tx*4 + j]; v[j] = Bs1[k][tx*4 + j]; }
            #pragma unroll
            for (int i = 0; i < 4; i++)
                #pragma unroll
                for (int j = 0; j < 4; j++)
                    acc[i][j] += a[i] * u[j] + c0v[i] * v[j];
        }
        __syncthreads();
    }
    #pragma unroll
    for (int i = 0; i < 4; i++) {
        float4 o;
        o.x = fmaxf(acc[i][0], 0.f); o.y = fmaxf(acc[i][1], 0.f);
        o.z = fmaxf(acc[i][2], 0.f); o.w = fmaxf(acc[i][3], 0.f);
        int d = d0 + ty*4 + i;
        *(float4*)&out[((size_t)b * Cc + d) * Nn + n0 + tx*4] = o;
    }
}

// ---------------------------------------------------------------------------
extern "C" void kernel_launch(void* const* d_in, const int* in_sizes, int n_in,
                              void* d_out, int out_size) {
    const float* x    = (const float*)d_in[0];
    const float* phi  = (const float*)d_in[1];
    const float* psi  = (const float*)d_in[2];
    const float* w0   = (const float*)d_in[3];
    const float* w1   = (const float*)d_in[4];
    float* out = (float*)d_out;

    cudaFuncSetAttribute(k_logits_mma,
                         cudaFuncAttributeMaxDynamicSharedMemorySize, SM_LOGITS_BYTES);

    k_pack<<<dim3(Nn/32, Cc/32, Bb), dim3(32, 8)>>>(x);
    k_qk<<<dim3(Cc/64, Nn/64, Bb), 256>>>(phi, psi);
    k_logits_mma<<<dim3(Nn/128, Nn/128, Bb), 256, SM_LOGITS_BYTES>>>();
    k_softmax_sparse<<<dim3(Nn, Bb), 256>>>();
    k_nbr_sparse<<<dim3(Nn, Bb), Cc>>>();
    k_final<<<dim3(Nn/64, Cc/64, Bb), 256>>>(w0, w1, out);
}

// round 5
// speedup vs baseline: 3.4108x; 1.5348x over previous
#include <cuda_runtime.h>
#include <cuda_bf16.h>
#include <cstdint>
#include <math.h>

#define Bb 8
#define Cc 256
#define Hh 48
#define Ww 48
#define Nn 2304
#define NC (Nn*Cc)
#define CAP 112
static const long long NNL = (long long)Nn * (long long)Nn;

// ---------------- scratch (static device globals — allocation-guard safe) ----
__device__ float g_X[Bb*NC];                     // (B,N,C) fp32
__device__ float g_diag[Bb*Nn];
__device__ float g_S[(long long)Bb*Nn*Nn];       // logits fp32
__device__ __nv_bfloat16 g_Xhi[Bb*NC], g_Xlo[Bb*NC];     // X (B,N,C) split
__device__ __nv_bfloat16 g_Qhi[Bb*NC], g_Qlo[Bb*NC];
__device__ __nv_bfloat16 g_Khi[Bb*NC], g_Klo[Bb*NC];
__device__ __nv_bfloat16 g_Xdh[Bb*NC], g_Xdl[Bb*NC];     // X*(1+diag) split
__device__ __nv_bfloat16 g_Nh[Bb*NC],  g_Nl[Bb*NC];      // nbr split
__device__ __nv_bfloat16 g_PhiH[Cc*Cc], g_PhiL[Cc*Cc];
__device__ __nv_bfloat16 g_PsiH[Cc*Cc], g_PsiL[Cc*Cc];
__device__ __nv_bfloat16 g_W0h[Cc*Cc], g_W0l[Cc*Cc];
__device__ __nv_bfloat16 g_W1h[Cc*Cc], g_W1l[Cc*Cc];
__device__ int   g_sidx[Bb*Nn*CAP];
__device__ float g_sval[Bb*Nn*CAP];
__device__ int   g_scnt[Bb*Nn];

// ---------------- PTX helpers (base-target features, sm_80 era) --------------
__device__ __forceinline__ uint32_t smem_u32(const void* p) {
    uint32_t a;
    asm("{ .reg .u64 t; cvta.to.shared.u64 t, %1; cvt.u32.u64 %0, t; }" : "=r"(a) : "l"(p));
    return a;
}
__device__ __forceinline__ void cp16(uint32_t dst, const void* src) {
    asm volatile("cp.async.cg.shared.global [%0], [%1], 16;" :: "r"(dst), "l"(src));
}
#define CP_COMMIT() asm volatile("cp.async.commit_group;" ::: "memory")
#define CP_WAIT(n)  asm volatile("cp.async.wait_group %0;" :: "n"(n) : "memory")

#define LDSM4(r, a) \
    asm volatile("ldmatrix.sync.aligned.m8n8.x4.shared.b16 {%0,%1,%2,%3}, [%4];" \
        : "=r"((r)[0]),"=r"((r)[1]),"=r"((r)[2]),"=r"((r)[3]) : "r"(a))
#define LDSM2(r, a) \
    asm volatile("ldmatrix.sync.aligned.m8n8.x2.shared.b16 {%0,%1}, [%2];" \
        : "=r"((r)[0]),"=r"((r)[1]) : "r"(a))
#define MMA16816(d, a, b) \
    asm volatile("mma.sync.aligned.m16n8k16.row.col.f32.bf16.bf16.f32 " \
        "{%0,%1,%2,%3}, {%4,%5,%6,%7}, {%8,%9}, {%0,%1,%2,%3};" \
        : "+f"((d)[0]),"+f"((d)[1]),"+f"((d)[2]),"+f"((d)[3]) \
        : "r"((a)[0]),"r"((a)[1]),"r"((a)[2]),"r"((a)[3]), "r"((b)[0]),"r"((b)[1]))

__device__ __forceinline__ void store_split2(__nv_bfloat16* hi, __nv_bfloat16* lo,
                                             size_t off, float a, float b) {
    __nv_bfloat16 ah = __float2bfloat16(a), bh = __float2bfloat16(b);
    __nv_bfloat162 h2; h2.x = ah; h2.y = bh;
    *(__nv_bfloat162*)(hi + off) = h2;
    __nv_bfloat162 l2;
    l2.x = __float2bfloat16(a - __bfloat162float(ah));
    l2.y = __float2bfloat16(b - __bfloat162float(bh));
    *(__nv_bfloat162*)(lo + off) = l2;
}

// ---------------------------------------------------------------------------
// 1) Pack: x (B,C,N) -> X (B,N,C) fp32 + bf16 hi/lo
// ---------------------------------------------------------------------------
__global__ void k_pack(const float* __restrict__ x) {
    __shared__ float t[32][33];
    int b = blockIdx.z;
    int n0 = blockIdx.x * 32, c0 = blockIdx.y * 32;
    int tx = threadIdx.x, ty = threadIdx.y;
    const float* xb = x + (size_t)b * Cc * Nn;
    #pragma unroll
    for (int i = 0; i < 4; i++)
        t[ty + 8*i][tx] = xb[(size_t)(c0 + ty + 8*i) * Nn + n0 + tx];
    __syncthreads();
    #pragma unroll
    for (int i = 0; i < 4; i++) {
        float v = t[tx][ty + 8*i];
        size_t o = (size_t)b * NC + (size_t)(n0 + ty + 8*i) * Cc + c0 + tx;
        g_X[o] = v;
        __nv_bfloat16 h = __float2bfloat16(v);
        g_Xhi[o] = h;
        g_Xlo[o] = __float2bfloat16(v - __bfloat162float(h));
    }
}

// ---------------------------------------------------------------------------
// 1b) Split all 4 weight matrices to bf16 hi/lo
// ---------------------------------------------------------------------------
__global__ void k_splitw(const float* __restrict__ phi, const float* __restrict__ psi,
                         const float* __restrict__ w0,  const float* __restrict__ w1) {
    int i = blockIdx.x * 256 + threadIdx.x;
    float v;
    __nv_bfloat16 h;
    v = phi[i]; h = __float2bfloat16(v); g_PhiH[i] = h; g_PhiL[i] = __float2bfloat16(v - __bfloat162float(h));
    v = psi[i]; h = __float2bfloat16(v); g_PsiH[i] = h; g_PsiL[i] = __float2bfloat16(v - __bfloat162float(h));
    v = w0[i];  h = __float2bfloat16(v); g_W0h[i]  = h; g_W0l[i]  = __float2bfloat16(v - __bfloat162float(h));
    v = w1[i];  h = __float2bfloat16(v); g_W1h[i]  = h; g_W1l[i]  = __float2bfloat16(v - __bfloat162float(h));
}

// ---------------------------------------------------------------------------
// 2) Q/K dual projection via HMMA 3-term split. CTA tile 128(tok) x 64(d).
// ---------------------------------------------------------------------------
#define QK_STAGE_E 20480
#define QK_SMEM (2*QK_STAGE_E*2)

__device__ __forceinline__ void qk_load_stage(__nv_bfloat16* sm, int st,
        const __nv_bfloat16* Xh, const __nv_bfloat16* Xl,
        const __nv_bfloat16* PhH, const __nv_bfloat16* PhL,
        const __nv_bfloat16* PsH, const __nv_bfloat16* PsL,
        int k0, int tid) {
    __nv_bfloat16* base = sm + st * QK_STAGE_E;
    const __nv_bfloat16* sa[2] = {Xh, Xl};
    #pragma unroll
    for (int t = 0; t < 2; t++) {
        __nv_bfloat16* dst = base + t * 5120;
        #pragma unroll
        for (int i = 0; i < 2; i++) {
            int chunk = i * 256 + tid;
            int r = chunk >> 2, c4 = chunk & 3;
            cp16(smem_u32(dst + r*40 + c4*8), sa[t] + (size_t)r*Cc + k0 + c4*8);
        }
    }
    const __nv_bfloat16* sb[4] = {PhH, PhL, PsH, PsL};
    int r = tid >> 2, c4 = tid & 3;
    #pragma unroll
    for (int t = 0; t < 4; t++) {
        __nv_bfloat16* dst = base + 10240 + t * 2560;
        cp16(smem_u32(dst + r*40 + c4*8), sb[t] + (size_t)r*Cc + k0 + c4*8);
    }
}

__global__ void __launch_bounds__(256) k_qk_mma() {
    extern __shared__ __nv_bfloat16 sm[];
    int tid = threadIdx.x, wid = tid >> 5, lane = tid & 31;
    int b = blockIdx.z;
    int arow = blockIdx.y * 128;
    int d0 = blockIdx.x * 64;

    const __nv_bfloat16* Xh = g_Xhi + (size_t)b*NC + (size_t)arow*Cc;
    const __nv_bfloat16* Xl = g_Xlo + (size_t)b*NC + (size_t)arow*Cc;
    const __nv_bfloat16* PhH = g_PhiH + (size_t)d0*Cc;
    const __nv_bfloat16* PhL = g_PhiL + (size_t)d0*Cc;
    const __nv_bfloat16* PsH = g_PsiH + (size_t)d0*Cc;
    const __nv_bfloat16* PsL = g_PsiL + (size_t)d0*Cc;

    int wm = (wid & 3) * 32;   // token offset
    int wn = (wid >> 2) * 32;  // d offset

    float accQ[2][4][4], accK[2][4][4];
    #pragma unroll
    for (int mi = 0; mi < 2; mi++)
        #pragma unroll
        for (int ni = 0; ni < 4; ni++)
            #pragma unroll
            for (int r = 0; r < 4; r++) { accQ[mi][ni][r] = 0.f; accK[mi][ni][r] = 0.f; }

    qk_load_stage(sm, 0, Xh, Xl, PhH, PhL, PsH, PsL, 0, tid);
    CP_COMMIT();

    for (int ch = 0; ch < 8; ch++) {
        if (ch < 7) {
            qk_load_stage(sm, (ch + 1) & 1, Xh, Xl, PhH, PhL, PsH, PsL, (ch + 1) * 32, tid);
            CP_COMMIT();
            CP_WAIT(1);
        } else {
            CP_WAIT(0);
        }
        __syncthreads();

        __nv_bfloat16* base = sm + (ch & 1) * QK_STAGE_E;
        const __nv_bfloat16* tXh = base;
        const __nv_bfloat16* tXl = base + 5120;
        const __nv_bfloat16* tPhH = base + 10240;
        const __nv_bfloat16* tPhL = base + 12800;
        const __nv_bfloat16* tPsH = base + 15360;
        const __nv_bfloat16* tPsL = base + 17920;

        int arl = lane & 15, ach = lane >> 4;
        int brl = lane & 7,  bch = (lane & 15) >> 3;

        #pragma unroll
        for (int ks = 0; ks < 2; ks++) {
            uint32_t bph[4][2], bpl[4][2], bsh[4][2], bsl[4][2];
            #pragma unroll
            for (int ni = 0; ni < 4; ni++) {
                LDSM2(bph[ni], smem_u32(tPhH + (wn + ni*8 + brl)*40 + ks*16 + bch*8));
                LDSM2(bpl[ni], smem_u32(tPhL + (wn + ni*8 + brl)*40 + ks*16 + bch*8));
                LDSM2(bsh[ni], smem_u32(tPsH + (wn + ni*8 + brl)*40 + ks*16 + bch*8));
                LDSM2(bsl[ni], smem_u32(tPsL + (wn + ni*8 + brl)*40 + ks*16 + bch*8));
            }
            #pragma unroll
            for (int mi = 0; mi < 2; mi++) {
                uint32_t xh[4], xl[4];
                LDSM4(xh, smem_u32(tXh + (wm + mi*16 + arl)*40 + ks*16 + ach*8));
                LDSM4(xl, smem_u32(tXl + (wm + mi*16 + arl)*40 + ks*16 + ach*8));
                #pragma unroll
                for (int ni = 0; ni < 4; ni++) {
                    MMA16816(accQ[mi][ni], xh, bph[ni]);
                    MMA16816(accQ[mi][ni], xh, bpl[ni]);
                    MMA16816(accQ[mi][ni], xl, bph[ni]);
                    MMA16816(accK[mi][ni], xh, bsh[ni]);
                    MMA16816(accK[mi][ni], xh, bsl[ni]);
                    MMA16816(accK[mi][ni], xl, bsh[ni]);
                }
            }
        }
        __syncthreads();
    }

    #pragma unroll
    for (int mi = 0; mi < 2; mi++)
        #pragma unroll
        for (int ni = 0; ni < 4; ni++) {
            int r0 = arow + wm + mi*16 + (lane >> 2);
            int c0v = d0 + wn + ni*8 + (lane & 3)*2;
            size_t o0 = (size_t)b*NC + (size_t)r0*Cc + c0v;
            size_t o1 = o0 + (size_t)8*Cc;
            store_split2(g_Qhi, g_Qlo, o0, accQ[mi][ni][0], accQ[mi][ni][1]);
            store_split2(g_Qhi, g_Qlo, o1, accQ[mi][ni][2], accQ[mi][ni][3]);
            store_split2(g_Khi, g_Klo, o0, accK[mi][ni][0], accK[mi][ni][1]);
            store_split2(g_Khi, g_Klo, o1, accK[mi][ni][2], accK[mi][ni][3]);
        }
}

// ---------------------------------------------------------------------------
// 3) Logits via HMMA 3-term: L = Q @ K^T  (128x128 CTA tile) [unchanged]
// ---------------------------------------------------------------------------
#define SSTR 40
#define TILE_E (128*SSTR)
#define SM_LOGITS_BYTES (2*4*TILE_E*2)

__device__ __forceinline__ void load_stage(__nv_bfloat16* sm, int stage,
        const __nv_bfloat16* Ah, const __nv_bfloat16* Al,
        const __nv_bfloat16* Bh, const __nv_bfloat16* Bl,
        int k0, int tid) {
    const __nv_bfloat16* srcs[4] = {Ah, Al, Bh, Bl};
    #pragma unroll
    for (int t = 0; t < 4; t++) {
        __nv_bfloat16* dst = sm + (stage*4 + t) * TILE_E;
        #pragma unroll
        for (int i = 0; i < 2; i++) {
            int chunk = i * 256 + tid;
            int r = chunk >> 2, c4 = chunk & 3;
            cp16(smem_u32(dst + r*SSTR + c4*8), srcs[t] + (size_t)r*Cc + k0 + c4*8);
        }
    }
}

__global__ void __launch_bounds__(256) k_logits_mma() {
    extern __shared__ __nv_bfloat16 sm[];
    int tid = threadIdx.x, wid = tid >> 5, lane = tid & 31;
    int b = blockIdx.z;
    int arow = blockIdx.y * 128;
    int brow = blockIdx.x * 128;

    const __nv_bfloat16* Ah = g_Qhi + (size_t)b*NC + (size_t)arow*Cc;
    const __nv_bfloat16* Al = g_Qlo + (size_t)b*NC + (size_t)arow*Cc;
    const __nv_bfloat16* Bh = g_Khi + (size_t)b*NC + (size_t)brow*Cc;
    const __nv_bfloat16* Bl = g_Klo + (size_t)b*NC + (size_t)brow*Cc;

    int wm = (wid & 1) * 64;
    int wn = (wid >> 1) * 32;

    float acc[4][4][4];
    #pragma unroll
    for (int mi = 0; mi < 4; mi++)
        #pragma unroll
        for (int ni = 0; ni < 4; ni++)
            #pragma unroll
            for (int r = 0; r < 4; r++) acc[mi][ni][r] = 0.f;

    load_stage(sm, 0, Ah, Al, Bh, Bl, 0, tid);
    CP_COMMIT();

    for (int ch = 0; ch < 8; ch++) {
        if (ch < 7) {
            load_stage(sm, (ch + 1) & 1, Ah, Al, Bh, Bl, (ch + 1) * 32, tid);
            CP_COMMIT();
            CP_WAIT(1);
        } else {
            CP_WAIT(0);
        }
        __syncthreads();

        int st = ch & 1;
        const __nv_bfloat16* tAh = sm + (st*4 + 0) * TILE_E;
        const __nv_bfloat16* tAl = sm + (st*4 + 1) * TILE_E;
        const __nv_bfloat16* tBh = sm + (st*4 + 2) * TILE_E;
        const __nv_bfloat16* tBl = sm + (st*4 + 3) * TILE_E;

        #pragma unroll
        for (int ks = 0; ks < 2; ks++) {
            uint32_t ah[4][4], al[4][4], bh[4][2], bl[4][2];
            int arl = lane & 15, ach = lane >> 4;
            int brl = lane & 7,  bch = (lane & 15) >> 3;
            #pragma unroll
            for (int mi = 0; mi < 4; mi++) {
                LDSM4(ah[mi], smem_u32(tAh + (wm + mi*16 + arl)*SSTR + ks*16 + ach*8));
                LDSM4(al[mi], smem_u32(tAl + (wm + mi*16 + arl)*SSTR + ks*16 + ach*8));
            }
            #pragma unroll
            for (int ni = 0; ni < 4; ni++) {
                LDSM2(bh[ni], smem_u32(tBh + (wn + ni*8 + brl)*SSTR + ks*16 + bch*8));
                LDSM2(bl[ni], smem_u32(tBl + (wn + ni*8 + brl)*SSTR + ks*16 + bch*8));
            }
            #pragma unroll
            for (int mi = 0; mi < 4; mi++)
                #pragma unroll
                for (int ni = 0; ni < 4; ni++) {
                    MMA16816(acc[mi][ni], ah[mi], bh[ni]);
                    MMA16816(acc[mi][ni], ah[mi], bl[ni]);
                    MMA16816(acc[mi][ni], al[mi], bh[ni]);
                }
        }
        __syncthreads();
    }

    float* Cp = g_S + (size_t)b * NNL;
    int r0 = arow + wm + (lane >> 2);
    int c0 = brow + wn + (lane & 3) * 2;
    #pragma unroll
    for (int mi = 0; mi < 4; mi++)
        #pragma unroll
        for (int ni = 0; ni < 4; ni++) {
            float* p0 = Cp + (size_t)(r0 + mi*16) * Nn + c0 + ni*8;
            p0[0] = acc[mi][ni][0]; p0[1] = acc[mi][ni][1];
            float* p1 = p0 + (size_t)8 * Nn;
            p1[0] = acc[mi][ni][2]; p1[1] = acc[mi][ni][3];
        }
}

// ---------------------------------------------------------------------------
// 4) Row softmax + threshold -> sparse list. Warp-chunk compaction, 4 syncs.
// ---------------------------------------------------------------------------
__global__ void __launch_bounds__(256) k_softmax_sparse() {
    __shared__ float ex[Nn];
    __shared__ float wred[8];
    __shared__ int wcnt[8], wbase[8];

    int b = blockIdx.y, n = blockIdx.x, tid = threadIdx.x;
    int wid = tid >> 5, lane = tid & 31;
    const float* row = g_S + (long long)b * NNL + (long long)n * Nn;

    float mx = -1e30f;
    for (int m = tid; m < Nn; m += 256) {
        float v = row[m];
        ex[m] = v;
        mx = fmaxf(mx, v);
    }
    #pragma unroll
    for (int o = 16; o; o >>= 1) mx = fmaxf(mx, __shfl_xor_sync(0xffffffffu, mx, o));
    if (!lane) wred[wid] = mx;
    __syncthreads();
    mx = wred[0];
    #pragma unroll
    for (int w = 1; w < 8; w++) mx = fmaxf(mx, wred[w]);
    __syncthreads();

    float s = 0.f;
    for (int m = tid; m < Nn; m += 256) {
        float e = __expf(ex[m] - mx);
        ex[m] = e;
        s += e;
    }
    #pragma unroll
    for (int o = 16; o; o >>= 1) s += __shfl_xor_sync(0xffffffffu, s, o);
    if (!lane) wred[wid] = s;
    __syncthreads();
    s = 0.f;
    #pragma unroll
    for (int w = 0; w < 8; w++) s += wred[w];
    float inv = 1.f / s;

    // compaction: warp wid owns [wid*288, wid*288+288)
    unsigned msks[9];
    int cnt = 0;
    int base_m = wid * 288;
    #pragma unroll
    for (int it = 0; it < 9; it++) {
        int m = base_m + it*32 + lane;
        float p = ex[m] * inv;
        bool ge = (p >= 0.01f);
        if (m == n) g_diag[b * Nn + n] = ge ? p : 0.f;
        bool keep = ge && (m != n);
        unsigned k = __ballot_sync(0xffffffffu, keep);
        msks[it] = k;
        cnt += __popc(k);
    }
    if (!lane) wcnt[wid] = cnt;
    __syncthreads();
    if (tid == 0) {
        int t = 0;
        #pragma unroll
        for (int w = 0; w < 8; w++) { wbase[w] = t; t += wcnt[w]; }
        g_scnt[b * Nn + n] = t;
    }
    __syncthreads();

    int* idx = g_sidx + ((size_t)b * Nn + n) * CAP;
    float* val = g_sval + ((size_t)b * Nn + n) * CAP;
    int bp = wbase[wid];
    #pragma unroll
    for (int it = 0; it < 9; it++) {
        unsigned k = msks[it];
        if ((k >> lane) & 1) {
            int m = base_m + it*32 + lane;
            int pos = bp + __popc(k & ((1u << lane) - 1));
            idx[pos] = m;
            val[pos] = ex[m] * inv;
        }
        bp += __popc(k);
    }
}

// ---------------------------------------------------------------------------
// 5) Sparse gather: nbr = S'@X + grid neighbors; emits nbr & Xd bf16 splits
// ---------------------------------------------------------------------------
__global__ void __launch_bounds__(256) k_nbr_gather() {
    int b = blockIdx.y, n = blockIdx.x, c = threadIdx.x;
    int y = n / Ww, x = n % Ww;
    const float* Xb = g_X + (size_t)b * NC;

    float acc = 0.f;
    if (y > 0)      acc += Xb[(size_t)(n - Ww) * Cc + c];
    if (y < Hh - 1) acc += Xb[(size_t)(n + Ww) * Cc + c];
    if (x > 0)      acc += Xb[(size_t)(n - 1) * Cc + c];
    if (x < Ww - 1) acc += Xb[(size_t)(n + 1) * Cc + c];

    int cnt = g_scnt[b * Nn + n];
    const int* idx = g_sidx + ((size_t)b * Nn + n) * CAP;
    const float* val = g_sval + ((size_t)b * Nn + n) * CAP;
    for (int i = 0; i < cnt; i++)
        acc += val[i] * Xb[(size_t)idx[i] * Cc + c];

    size_t o = (size_t)b * NC + (size_t)n * Cc + c;
    __nv_bfloat16 nh = __float2bfloat16(acc);
    g_Nh[o] = nh;
    g_Nl[o] = __float2bfloat16(acc - __bfloat162float(nh));

    float xd = Xb[(size_t)n * Cc + c] * (1.f + g_diag[b * Nn + n]);
    __nv_bfloat16 xh = __float2bfloat16(xd);
    g_Xdh[o] = xh;
    g_Xdl[o] = __float2bfloat16(xd - __bfloat162float(xh));
}

// ---------------------------------------------------------------------------
// 6) Final: out = relu(w0@Xd^T + w1@nbr^T) via HMMA 6-term. CTA 128(d)x128(n)
// ---------------------------------------------------------------------------
#define FIN_STAGE_E 40960
#define FIN_SMEM (2*FIN_STAGE_E*2)

__global__ void __launch_bounds__(256) k_final_mma(float* __restrict__ out) {
    extern __shared__ __nv_bfloat16 sm[];
    int tid = threadIdx.x, wid = tid >> 5, lane = tid & 31;
    int b = blockIdx.z;
    int d0 = blockIdx.y * 128;
    int n0 = blockIdx.x * 128;

    const __nv_bfloat16* srcs[8] = {
        g_W0h + (size_t)d0*Cc, g_W0l + (size_t)d0*Cc,
        g_W1h + (size_t)d0*Cc, g_W1l + (size_t)d0*Cc,
        g_Xdh + (size_t)b*NC + (size_t)n0*Cc, g_Xdl + (size_t)b*NC + (size_t)n0*Cc,
        g_Nh  + (size_t)b*NC + (size_t)n0*Cc, g_Nl  + (size_t)b*NC + (size_t)n0*Cc
    };

    int wm = (wid & 1) * 64;
    int wn = (wid >> 1) * 32;

    float acc[4][4][4];
    #pragma unroll
    for (int mi = 0; mi < 4; mi++)
        #pragma unroll
        for (int ni = 0; ni < 4; ni++)
            #pragma unroll
            for (int r = 0; r < 4; r++) acc[mi][ni][r] = 0.f;

    // stage load: 8 tiles of 128x32
    auto load_fin = [&](int st, int k0) {
        __nv_bfloat16* base = sm + st * FIN_STAGE_E;
        #pragma unroll
        for (int t = 0; t < 8; t++) {
            __nv_bfloat16* dst = base + t * 5120;
            #pragma unroll
            for (int i = 0; i < 2; i++) {
                int chunk = i * 256 + tid;
                int r = chunk >> 2, c4 = chunk & 3;
                cp16(smem_u32(dst + r*40 + c4*8), srcs[t] + (size_t)r*Cc + k0 + c4*8);
            }
        }
    };

    load_fin(0, 0);
    CP_COMMIT();

    for (int ch = 0; ch < 8; ch++) {
        if (ch < 7) {
            load_fin((ch + 1) & 1, (ch + 1) * 32);
            CP_COMMIT();
            CP_WAIT(1);
        } else {
            CP_WAIT(0);
        }
        __syncthreads();

        __nv_bfloat16* base = sm + (ch & 1) * FIN_STAGE_E;
        const __nv_bfloat16* tW0h = base;
        const __nv_bfloat16* tW0l = base + 5120;
        const __nv_bfloat16* tW1h = base + 10240;
        const __nv_bfloat16* tW1l = base + 15360;
        const __nv_bfloat16* tXh  = base + 20480;
        const __nv_bfloat16* tXl  = base + 25600;
        const __nv_bfloat16* tNh  = base + 30720;
        const __nv_bfloat16* tNl  = base + 35840;

        int arl = lane & 15, ach = lane >> 4;
        int brl = lane & 7,  bch = (lane & 15) >> 3;

        #pragma unroll
        for (int ks = 0; ks < 2; ks++) {
            uint32_t bxh[4][2], bxl[4][2], bnh[4][2], bnl[4][2];
            #pragma unroll
            for (int ni = 0; ni < 4; ni++) {
                LDSM2(bxh[ni], smem_u32(tXh + (wn + ni*8 + brl)*40 + ks*16 + bch*8));
                LDSM2(bxl[ni], smem_u32(tXl + (wn + ni*8 + brl)*40 + ks*16 + bch*8));
                LDSM2(bnh[ni], smem_u32(tNh + (wn + ni*8 + brl)*40 + ks*16 + bch*8));
                LDSM2(bnl[ni], smem_u32(tNl + (wn + ni*8 + brl)*40 + ks*16 + bch*8));
            }
            #pragma unroll
            for (int mi = 0; mi < 4; mi++) {
                uint32_t w0h[4], w0l[4], w1h[4], w1l[4];
                LDSM4(w0h, smem_u32(tW0h + (wm + mi*16 + arl)*40 + ks*16 + ach*8));
                LDSM4(w0l, smem_u32(tW0l + (wm + mi*16 + arl)*40 + ks*16 + ach*8));
                LDSM4(w1h, smem_u32(tW1h + (wm + mi*16 + arl)*40 + ks*16 + ach*8));
                LDSM4(w1l, smem_u32(tW1l + (wm + mi*16 + arl)*40 + ks*16 + ach*8));
                #pragma unroll
                for (int ni = 0; ni < 4; ni++) {
                    MMA16816(acc[mi][ni], w0h, bxh[ni]);
                    MMA16816(acc[mi][ni], w0h, bxl[ni]);
                    MMA16816(acc[mi][ni], w0l, bxh[ni]);
                    MMA16816(acc[mi][ni], w1h, bnh[ni]);
                    MMA16816(acc[mi][ni], w1h, bnl[ni]);
                    MMA16816(acc[mi][ni], w1l, bnh[ni]);
                }
            }
        }
        __syncthreads();
    }

    #pragma unroll
    for (int mi = 0; mi < 4; mi++)
        #pragma unroll
        for (int ni = 0; ni < 4; ni++) {
            int d = d0 + wm + mi*16 + (lane >> 2);
            int col = n0 + wn + ni*8 + (lane & 3)*2;
            float* p0 = out + ((size_t)b * Cc + d) * Nn + col;
            float2 v0;
            v0.x = fmaxf(acc[mi][ni][0], 0.f);
            v0.y = fmaxf(acc[mi][ni][1], 0.f);
            *(float2*)p0 = v0;
            float2 v1;
            v1.x = fmaxf(acc[mi][ni][2], 0.f);
            v1.y = fmaxf(acc[mi][ni][3], 0.f);
            *(float2*)(p0 + (size_t)8 * Nn) = v1;
        }
}

// ---------------------------------------------------------------------------
extern "C" void kernel_launch(void* const* d_in, const int* in_sizes, int n_in,
                              void* d_out, int out_size) {
    const float* x    = (const float*)d_in[0];
    const float* phi  = (const float*)d_in[1];
    const float* psi  = (const float*)d_in[2];
    const float* w0   = (const float*)d_in[3];
    const float* w1   = (const float*)d_in[4];
    float* out = (float*)d_out;

    cudaFuncSetAttribute(k_qk_mma,     cudaFuncAttributeMaxDynamicSharedMemorySize, QK_SMEM);
    cudaFuncSetAttribute(k_logits_mma, cudaFuncAttributeMaxDynamicSharedMemorySize, SM_LOGITS_BYTES);
    cudaFuncSetAttribute(k_final_mma,  cudaFuncAttributeMaxDynamicSharedMemorySize, FIN_SMEM);

    k_pack<<<dim3(Nn/32, Cc/32, Bb), dim3(32, 8)>>>(x);
    k_splitw<<<(Cc*Cc)/256, 256>>>(phi, psi, w0, w1);
    k_qk_mma<<<dim3(Cc/64, Nn/128, Bb), 256, QK_SMEM>>>();
    k_logits_mma<<<dim3(Nn/128, Nn/128, Bb), 256, SM_LOGITS_BYTES>>>();
    k_softmax_sparse<<<dim3(Nn, Bb), 256>>>();
    k_nbr_gather<<<dim3(Nn, Bb), 256>>>();
    k_final_mma<<<dim3(Nn/128, Cc/128, Bb), 256, FIN_SMEM>>>(out);
}